// round 6
// baseline (speedup 1.0000x reference)
#include <cuda_runtime.h>
#include <cuda_fp16.h>
#include <cstdint>

// ============================================================================
// Problem constants
// ============================================================================
#define N_NODES 10000
#define N_EDGES 160000
#define D_IN    512
#define D_HID   1024
#define NB_SCAN 40   // ceil(N_NODES/256)

// ============================================================================
// Scratch (static __device__ arrays — no allocation allowed)
// ============================================================================
__device__ __half g_Ah[(size_t)N_NODES * D_IN];    // rst hi   [N, 512]
__device__ __half g_Al[(size_t)N_NODES * D_IN];    // rst lo
__device__ __half g_Hh[(size_t)N_NODES * D_HID];   // hidden hi [N, 1024]
__device__ __half g_Hl[(size_t)N_NODES * D_HID];   // hidden lo
__device__ __half g_W1h[(size_t)D_HID * D_IN];     // W1^T hi [1024, 512]
__device__ __half g_W1l[(size_t)D_HID * D_IN];
__device__ __half g_W2h[(size_t)D_IN * D_HID];     // W2^T hi [512, 1024]
__device__ __half g_W2l[(size_t)D_IN * D_HID];
__device__ int   g_cnt[N_NODES];
__device__ int   g_off[N_NODES + 1];
__device__ int   g_cur[N_NODES];
__device__ int   g_csr[N_EDGES];
__device__ int   g_bsum[NB_SCAN];
__device__ int   g_bpre[NB_SCAN];

// ============================================================================
// Helpers
// ============================================================================
__device__ __forceinline__ uint32_t smem_to_u32(const void* p) {
    uint32_t a;
    asm("{ .reg .u64 t; cvta.to.shared.u64 t, %1; cvt.u32.u64 %0, t; }" : "=r"(a) : "l"(p));
    return a;
}

__device__ __forceinline__ void split_h(float x, __half& h, __half& l) {
    h = __float2half_rn(x);
    l = __float2half_rn(x - __half2float(h));
}

__device__ __forceinline__ void ldsm_x4(uint32_t& r0, uint32_t& r1, uint32_t& r2, uint32_t& r3,
                                        uint32_t addr) {
    asm volatile("ldmatrix.sync.aligned.m8n8.x4.shared.b16 {%0,%1,%2,%3}, [%4];"
                 : "=r"(r0), "=r"(r1), "=r"(r2), "=r"(r3) : "r"(addr));
}

// ============================================================================
// Graph preprocessing kernels (CSR build)
// ============================================================================
__global__ void zero_cnt_kernel() {
    int i = blockIdx.x * blockDim.x + threadIdx.x;
    if (i < N_NODES) g_cnt[i] = 0;
}

__global__ void hist_kernel(const int* __restrict__ dst) {
    int i = blockIdx.x * blockDim.x + threadIdx.x;
    if (i < N_EDGES) atomicAdd(&g_cnt[dst[i]], 1);
}

// hierarchical scan: per-block reduce -> tiny serial scan -> per-block scan
__global__ void block_reduce_kernel() {
    __shared__ int ws[8];
    int t = threadIdx.x, b = blockIdx.x;
    int i = b * 256 + t;
    int v = (i < N_NODES) ? g_cnt[i] : 0;
    #pragma unroll
    for (int o = 16; o > 0; o >>= 1) v += __shfl_down_sync(0xFFFFFFFFu, v, o);
    if ((t & 31) == 0) ws[t >> 5] = v;
    __syncthreads();
    if (t == 0) {
        int s = 0;
        #pragma unroll
        for (int j = 0; j < 8; j++) s += ws[j];
        g_bsum[b] = s;
    }
}

__global__ void scan_bsums_kernel() {
    if (threadIdx.x == 0) {
        int s = 0;
        for (int j = 0; j < NB_SCAN; j++) { g_bpre[j] = s; s += g_bsum[j]; }
        g_off[N_NODES] = s;
    }
}

__global__ void block_scan_kernel() {
    __shared__ int ws[8];
    int t = threadIdx.x, b = blockIdx.x;
    int i = b * 256 + t;
    int v = (i < N_NODES) ? g_cnt[i] : 0;
    int x = v;
    #pragma unroll
    for (int o = 1; o < 32; o <<= 1) {
        int y = __shfl_up_sync(0xFFFFFFFFu, x, o);
        if ((t & 31) >= o) x += y;
    }
    if ((t & 31) == 31) ws[t >> 5] = x;
    __syncthreads();
    if (t == 0) {
        int s = 0;
        #pragma unroll
        for (int j = 0; j < 8; j++) { int tmp = ws[j]; ws[j] = s; s += tmp; }
    }
    __syncthreads();
    int ex = g_bpre[b] + ws[t >> 5] + x - v;
    if (i < N_NODES) { g_off[i] = ex; g_cur[i] = ex; }
}

__global__ void scatter_kernel(const int* __restrict__ src, const int* __restrict__ dst) {
    int i = blockIdx.x * blockDim.x + threadIdx.x;
    if (i < N_EDGES) {
        int d = dst[i];
        int p = atomicAdd(&g_cur[d], 1);
        g_csr[p] = src[i];
    }
}

// ============================================================================
// Aggregate: warp-per-node gather-sum + GIN combine -> split hi/lo fp16
// ============================================================================
__device__ __forceinline__ void f4add(float4& a, const float4 b) {
    a.x += b.x; a.y += b.y; a.z += b.z; a.w += b.w;
}

__device__ __forceinline__ void store_split4(__half* ph, __half* pl, size_t off, float4 v) {
    __half hx, hy, hz, hw, lx, ly, lz, lw;
    split_h(v.x, hx, lx); split_h(v.y, hy, ly);
    split_h(v.z, hz, lz); split_h(v.w, hw, lw);
    *(__half2*)(ph + off)     = __halves2half2(hx, hy);
    *(__half2*)(ph + off + 2) = __halves2half2(hz, hw);
    *(__half2*)(pl + off)     = __halves2half2(lx, ly);
    *(__half2*)(pl + off + 2) = __halves2half2(lz, lw);
}

__global__ __launch_bounds__(256) void aggregate_kernel(const float* __restrict__ feat,
                                                        const float* __restrict__ eps) {
    int wid = threadIdx.x >> 5, lane = threadIdx.x & 31;
    int node = blockIdx.x * 8 + wid;
    if (node >= N_NODES) return;

    float4 a0 = make_float4(0.f, 0.f, 0.f, 0.f), a1 = a0, a2 = a0, a3 = a0;
    int e = g_off[node], e1 = g_off[node + 1];
    const float4* F = (const float4*)feat;

    for (; e + 1 < e1; e += 2) {
        const float4* p0 = F + (size_t)g_csr[e]     * (D_IN / 4);
        const float4* p1 = F + (size_t)g_csr[e + 1] * (D_IN / 4);
        float4 v00 = p0[lane], v01 = p0[lane + 32], v02 = p0[lane + 64], v03 = p0[lane + 96];
        float4 v10 = p1[lane], v11 = p1[lane + 32], v12 = p1[lane + 64], v13 = p1[lane + 96];
        f4add(a0, v00); f4add(a1, v01); f4add(a2, v02); f4add(a3, v03);
        f4add(a0, v10); f4add(a1, v11); f4add(a2, v12); f4add(a3, v13);
    }
    if (e < e1) {
        const float4* p0 = F + (size_t)g_csr[e] * (D_IN / 4);
        f4add(a0, p0[lane]); f4add(a1, p0[lane + 32]);
        f4add(a2, p0[lane + 64]); f4add(a3, p0[lane + 96]);
    }

    float ep = 1.0f + eps[0];
    const float4* fn = F + (size_t)node * (D_IN / 4);
    float4 f0 = fn[lane], f1 = fn[lane + 32], f2 = fn[lane + 64], f3 = fn[lane + 96];
    float4 r0 = make_float4(fmaf(ep, f0.x, a0.x), fmaf(ep, f0.y, a0.y), fmaf(ep, f0.z, a0.z), fmaf(ep, f0.w, a0.w));
    float4 r1 = make_float4(fmaf(ep, f1.x, a1.x), fmaf(ep, f1.y, a1.y), fmaf(ep, f1.z, a1.z), fmaf(ep, f1.w, a1.w));
    float4 r2 = make_float4(fmaf(ep, f2.x, a2.x), fmaf(ep, f2.y, a2.y), fmaf(ep, f2.z, a2.z), fmaf(ep, f2.w, a2.w));
    float4 r3 = make_float4(fmaf(ep, f3.x, a3.x), fmaf(ep, f3.y, a3.y), fmaf(ep, f3.z, a3.z), fmaf(ep, f3.w, a3.w));

    size_t base = (size_t)node * D_IN;
    store_split4(g_Ah, g_Al, base + lane * 4,        r0);
    store_split4(g_Ah, g_Al, base + (lane + 32) * 4, r1);
    store_split4(g_Ah, g_Al, base + (lane + 64) * 4, r2);
    store_split4(g_Ah, g_Al, base + (lane + 96) * 4, r3);
}

// ============================================================================
// Weight transpose + split: outh/outl[c][r] = split(in[r][c])
// ============================================================================
__global__ void transpose_split_kernel(const float* __restrict__ in,
                                       __half* __restrict__ outh, __half* __restrict__ outl,
                                       int R, int C) {
    __shared__ float t[32][33];
    int bx = blockIdx.x * 32, by = blockIdx.y * 32;
    int tx = threadIdx.x, ty = threadIdx.y;
    #pragma unroll
    for (int j = 0; j < 32; j += 8)
        t[ty + j][tx] = in[(size_t)(by + ty + j) * C + bx + tx];
    __syncthreads();
    #pragma unroll
    for (int j = 0; j < 32; j += 8) {
        float x = t[tx][ty + j];
        __half h, l; split_h(x, h, l);
        size_t o = (size_t)(bx + ty + j) * R + by + tx;
        outh[o] = h; outl[o] = l;
    }
}

// ============================================================================
// 3xFP16 mma.sync GEMM v2: BM=128, BN=256, BK=32, 256 threads, 2x4 warp grid,
// 64x64 warp tiles, ldmatrix.x4 fragment loads, 3-slot cp.async pipeline.
// acc += Ah*Bh + Ah*Bl + Al*Bh  (f32 accum; lo*lo dropped).
// ============================================================================
#define BM 128
#define BN 256
#define BK 32
#define HROW  40                      // halfs per smem row (32 + 4 pad)
#define HROWB 80                      // bytes per smem row
#define AH_OFF 0
#define AL_OFF (128 * HROWB)
#define BH_OFF (256 * HROWB)
#define BL_OFF (512 * HROWB)
#define STAGE_B (768 * HROWB)         // 61440 bytes per stage
#define GEMM_SMEM (3 * STAGE_B)       // 184320

__device__ __forceinline__ void cp_async16(uint32_t dst, const void* src, int src_sz) {
    asm volatile("cp.async.ca.shared.global [%0], [%1], 16, %2;"
                 :: "r"(dst), "l"(src), "r"(src_sz));
}

__device__ __forceinline__ void load_stage(uint32_t st,
                                           const __half* __restrict__ Ah, const __half* __restrict__ Al,
                                           const __half* __restrict__ Bh, const __half* __restrict__ Bl,
                                           int M, int K, int m0, int n0, int k0, int tid) {
    // A: 128 rows x 32 halfs (4 x 16B chunks per row), hi + lo
    #pragma unroll
    for (int i = 0; i < 2; i++) {
        int idx = tid + i * 256;
        int row = idx >> 2, c = idx & 3;
        uint32_t doff = (uint32_t)(row * HROWB + c * 16);
        int gm = m0 + row;
        int ok = gm < M;
        size_t goff = (size_t)(ok ? gm : 0) * K + k0 + c * 8;
        cp_async16(st + AH_OFF + doff, Ah + goff, ok ? 16 : 0);
        cp_async16(st + AL_OFF + doff, Al + goff, ok ? 16 : 0);
    }
    // B: 256 rows x 32 halfs, hi + lo   (N multiple of BN -> no guard)
    #pragma unroll
    for (int i = 0; i < 4; i++) {
        int idx = tid + i * 256;
        int row = idx >> 2, c = idx & 3;
        uint32_t doff = (uint32_t)(row * HROWB + c * 16);
        size_t goff = (size_t)(n0 + row) * K + k0 + c * 8;
        cp_async16(st + BH_OFF + doff, Bh + goff, 16);
        cp_async16(st + BL_OFF + doff, Bl + goff, 16);
    }
}

__device__ __forceinline__ void mma_f16(float d[4], const uint32_t a[4], const uint32_t b[2]) {
    asm volatile(
        "mma.sync.aligned.m16n8k16.row.col.f32.f16.f16.f32 "
        "{%0,%1,%2,%3}, {%4,%5,%6,%7}, {%8,%9}, {%0,%1,%2,%3};"
        : "+f"(d[0]), "+f"(d[1]), "+f"(d[2]), "+f"(d[3])
        : "r"(a[0]), "r"(a[1]), "r"(a[2]), "r"(a[3]), "r"(b[0]), "r"(b[1]));
}

__global__ __launch_bounds__(256, 1) void gemm_3xh_kernel(
    const __half* __restrict__ Ah, const __half* __restrict__ Al,
    const __half* __restrict__ Bh, const __half* __restrict__ Bl,
    const float* __restrict__ bias, const float* __restrict__ residual,
    float* __restrict__ out, __half* __restrict__ outh, __half* __restrict__ outl,
    int M, int K, int N, int do_relu)
{
    extern __shared__ char smem[];
    uint32_t sb = smem_to_u32(smem);
    const int tid = threadIdx.x, wid = tid >> 5, lane = tid & 31;
    const int m0 = blockIdx.y * BM, n0 = blockIdx.x * BN;
    const int wm = wid & 1, wn = wid >> 1;       // warp tile: 64 (m) x 64 (n)
    const int lg = lane >> 2, lt = lane & 3;

    // ldmatrix per-lane address offsets (within a 16x16 subtile)
    const uint32_t aLane = (uint32_t)((lane & 15) * HROWB + (lane >> 4) * 16);
    const uint32_t bLane = (uint32_t)((((lane >> 4) << 3) + (lane & 7)) * HROWB
                                      + ((lane >> 3) & 1) * 16);

    float acc[4][8][4];
    #pragma unroll
    for (int i = 0; i < 4; i++)
        #pragma unroll
        for (int j = 0; j < 8; j++)
            #pragma unroll
            for (int c = 0; c < 4; c++) acc[i][j][c] = 0.f;

    const int nk = K / BK;
    load_stage(sb, Ah, Al, Bh, Bl, M, K, m0, n0, 0, tid);
    asm volatile("cp.async.commit_group;" ::: "memory");
    load_stage(sb + STAGE_B, Ah, Al, Bh, Bl, M, K, m0, n0, BK, tid);
    asm volatile("cp.async.commit_group;" ::: "memory");

    for (int kc = 0; kc < nk; kc++) {
        asm volatile("cp.async.wait_group 1;" ::: "memory");
        __syncthreads();
        // prefetch stage kc+2 into slot (kc+2)%3 (freed by compute of kc-1)
        if (kc + 2 < nk)
            load_stage(sb + ((kc + 2) % 3) * STAGE_B, Ah, Al, Bh, Bl,
                       M, K, m0, n0, (kc + 2) * BK, tid);
        asm volatile("cp.async.commit_group;" ::: "memory");

        const uint32_t st = sb + (kc % 3) * STAGE_B;
        const uint32_t aBaseH = st + AH_OFF + (uint32_t)(wm * 64) * HROWB + aLane;
        const uint32_t aBaseL = st + AL_OFF + (uint32_t)(wm * 64) * HROWB + aLane;
        const uint32_t bBaseH = st + BH_OFF + (uint32_t)(wn * 64) * HROWB + bLane;
        const uint32_t bBaseL = st + BL_OFF + (uint32_t)(wn * 64) * HROWB + bLane;

        #pragma unroll
        for (int kk = 0; kk < BK; kk += 16) {
            uint32_t bh[8][2], bl[8][2];
            #pragma unroll
            for (int njp = 0; njp < 4; njp++) {
                uint32_t o = (uint32_t)(njp * 16 * HROWB + kk * 2);
                ldsm_x4(bh[2 * njp][0], bh[2 * njp][1], bh[2 * njp + 1][0], bh[2 * njp + 1][1],
                        bBaseH + o);
                ldsm_x4(bl[2 * njp][0], bl[2 * njp][1], bl[2 * njp + 1][0], bl[2 * njp + 1][1],
                        bBaseL + o);
            }
            #pragma unroll
            for (int mi = 0; mi < 4; mi++) {
                uint32_t o = (uint32_t)(mi * 16 * HROWB + kk * 2);
                uint32_t ah[4], al[4];
                ldsm_x4(ah[0], ah[1], ah[2], ah[3], aBaseH + o);
                ldsm_x4(al[0], al[1], al[2], al[3], aBaseL + o);
                #pragma unroll
                for (int nj = 0; nj < 8; nj++) {
                    mma_f16(acc[mi][nj], ah, bl[nj]);   // hi*lo
                    mma_f16(acc[mi][nj], al, bh[nj]);   // lo*hi
                    mma_f16(acc[mi][nj], ah, bh[nj]);   // hi*hi
                }
            }
        }
    }

    // ---- Epilogue
    #pragma unroll
    for (int mi = 0; mi < 4; mi++) {
        #pragma unroll
        for (int half = 0; half < 2; half++) {
            int gm = m0 + wm * 64 + mi * 16 + lg + half * 8;
            if (gm >= M) continue;
            #pragma unroll
            for (int nj = 0; nj < 8; nj++) {
                int gn = n0 + wn * 64 + nj * 8 + 2 * lt;
                float vx = acc[mi][nj][half * 2 + 0];
                float vy = acc[mi][nj][half * 2 + 1];
                float2 bv = *(const float2*)(bias + gn);
                vx += bv.x; vy += bv.y;
                if (do_relu) { vx = fmaxf(vx, 0.f); vy = fmaxf(vy, 0.f); }
                if (outh) {
                    __half hx, hy, lx, ly;
                    split_h(vx, hx, lx); split_h(vy, hy, ly);
                    *(__half2*)(outh + (size_t)gm * N + gn) = __halves2half2(hx, hy);
                    *(__half2*)(outl + (size_t)gm * N + gn) = __halves2half2(lx, ly);
                } else {
                    if (residual) {
                        float2 rv = *(const float2*)(residual + (size_t)gm * N + gn);
                        vx += rv.x; vy += rv.y;
                    }
                    *(float2*)(out + (size_t)gm * N + gn) = make_float2(vx, vy);
                }
            }
        }
    }
}

// ============================================================================
// kernel_launch
// ============================================================================
extern "C" void kernel_launch(void* const* d_in, const int* in_sizes, int n_in,
                              void* d_out, int out_size) {
    const float* feat = (const float*)d_in[0];
    const float* W1   = (const float*)d_in[1];
    const float* b1   = (const float*)d_in[2];
    const float* W2   = (const float*)d_in[3];
    const float* b2   = (const float*)d_in[4];
    const float* eps  = (const float*)d_in[5];
    const int*   src  = (const int*)d_in[6];
    const int*   dst  = (const int*)d_in[7];
    float* out = (float*)d_out;

    __half *p_Ah, *p_Al, *p_Hh, *p_Hl, *p_W1h, *p_W1l, *p_W2h, *p_W2l;
    cudaGetSymbolAddress((void**)&p_Ah,  g_Ah);
    cudaGetSymbolAddress((void**)&p_Al,  g_Al);
    cudaGetSymbolAddress((void**)&p_Hh,  g_Hh);
    cudaGetSymbolAddress((void**)&p_Hl,  g_Hl);
    cudaGetSymbolAddress((void**)&p_W1h, g_W1h);
    cudaGetSymbolAddress((void**)&p_W1l, g_W1l);
    cudaGetSymbolAddress((void**)&p_W2h, g_W2h);
    cudaGetSymbolAddress((void**)&p_W2l, g_W2l);

    cudaFuncSetAttribute(gemm_3xh_kernel,
                         cudaFuncAttributeMaxDynamicSharedMemorySize, GEMM_SMEM);

    // --- CSR build
    zero_cnt_kernel<<<(N_NODES + 255) / 256, 256>>>();
    hist_kernel<<<N_EDGES / 256, 256>>>(dst);
    block_reduce_kernel<<<NB_SCAN, 256>>>();
    scan_bsums_kernel<<<1, 32>>>();
    block_scan_kernel<<<NB_SCAN, 256>>>();
    scatter_kernel<<<N_EDGES / 256, 256>>>(src, dst);

    // --- Weight transpose + split
    transpose_split_kernel<<<dim3(D_HID / 32, D_IN / 32), dim3(32, 8)>>>(W1, p_W1h, p_W1l, D_IN, D_HID);
    transpose_split_kernel<<<dim3(D_IN / 32, D_HID / 32), dim3(32, 8)>>>(W2, p_W2h, p_W2l, D_HID, D_IN);

    // --- Aggregate + GIN combine (writes split rst)
    aggregate_kernel<<<(N_NODES + 7) / 8, 256>>>(feat, eps);

    // --- GEMM1: H = relu(rst @ W1 + b1), written split  [10000,512]@[512,1024]
    gemm_3xh_kernel<<<dim3(D_HID / BN, (N_NODES + BM - 1) / BM), 256, GEMM_SMEM>>>(
        p_Ah, p_Al, p_W1h, p_W1l, b1, nullptr, nullptr, p_Hh, p_Hl,
        N_NODES, D_IN, D_HID, 1);

    // --- GEMM2: out = H @ W2 + b2 + feat  [10000,1024]@[1024,512]
    gemm_3xh_kernel<<<dim3(D_IN / BN, (N_NODES + BM - 1) / BM), 256, GEMM_SMEM>>>(
        p_Hh, p_Hl, p_W2h, p_W2l, b2, feat, out, nullptr, nullptr,
        N_NODES, D_HID, D_IN, 0);
}

// round 7
// speedup vs baseline: 1.1275x; 1.1275x over previous
#include <cuda_runtime.h>
#include <cuda_fp16.h>
#include <cstdint>

// ============================================================================
// Problem constants
// ============================================================================
#define N_NODES 10000
#define N_EDGES 160000
#define D_IN    512
#define D_HID   1024
#define NB_SCAN 40   // ceil(N_NODES/256)

// ============================================================================
// Scratch (static __device__ arrays — no allocation allowed)
// ============================================================================
__device__ __half g_Ah[(size_t)N_NODES * D_IN];    // rst hi   [N, 512]
__device__ __half g_Al[(size_t)N_NODES * D_IN];    // rst lo
__device__ __half g_Hh[(size_t)N_NODES * D_HID];   // hidden hi [N, 1024]
__device__ __half g_Hl[(size_t)N_NODES * D_HID];   // hidden lo
__device__ __half g_W1h[(size_t)D_HID * D_IN];     // W1^T hi [1024, 512]
__device__ __half g_W1l[(size_t)D_HID * D_IN];
__device__ __half g_W2h[(size_t)D_IN * D_HID];     // W2^T hi [512, 1024]
__device__ __half g_W2l[(size_t)D_IN * D_HID];
__device__ int   g_cnt[N_NODES];
__device__ int   g_off[N_NODES];
__device__ int   g_cur[N_NODES];
__device__ int   g_csr[N_EDGES];
__device__ int   g_base_ctr;

// ============================================================================
// Helpers
// ============================================================================
__device__ __forceinline__ uint32_t smem_to_u32(const void* p) {
    uint32_t a;
    asm("{ .reg .u64 t; cvta.to.shared.u64 t, %1; cvt.u32.u64 %0, t; }" : "=r"(a) : "l"(p));
    return a;
}

__device__ __forceinline__ void split_h(float x, __half& h, __half& l) {
    h = __float2half_rn(x);
    l = __float2half_rn(x - __half2float(h));
}

// ============================================================================
// prep_kernel (launch 0): zero g_cnt + reset base counter + both W transposes.
// Grid = 40 (zero) + 512 (W1^T) + 512 (W2^T) blocks of (32, 8).
// ============================================================================
__device__ __forceinline__ void transpose_split_tile(const float* __restrict__ in,
                                                     __half* __restrict__ outh,
                                                     __half* __restrict__ outl,
                                                     int R, int C, int bx, int by,
                                                     float* tbuf /* 32*33 */) {
    int tx = threadIdx.x, ty = threadIdx.y;
    #pragma unroll
    for (int j = 0; j < 32; j += 8)
        tbuf[(ty + j) * 33 + tx] = in[(size_t)(by + ty + j) * C + bx + tx];
    __syncthreads();
    #pragma unroll
    for (int j = 0; j < 32; j += 8) {
        float x = tbuf[tx * 33 + ty + j];
        __half h, l; split_h(x, h, l);
        size_t o = (size_t)(bx + ty + j) * R + by + tx;
        outh[o] = h; outl[o] = l;
    }
}

__global__ void prep_kernel(const float* __restrict__ W1, const float* __restrict__ W2) {
    __shared__ float tbuf[32 * 33];
    int b = blockIdx.x;
    int t = threadIdx.y * 32 + threadIdx.x;
    if (b < NB_SCAN) {
        int i = b * 256 + t;
        if (i < N_NODES) g_cnt[i] = 0;
        if (b == 0 && t == 0) g_base_ctr = 0;
    } else if (b < NB_SCAN + 512) {
        int idx = b - NB_SCAN;                     // W1: [512,1024] -> W1^T [1024,512]
        int bx = (idx & 31) * 32, by = (idx >> 5) * 32;
        transpose_split_tile(W1, g_W1h, g_W1l, D_IN, D_HID, bx, by, tbuf);
    } else {
        int idx = b - NB_SCAN - 512;               // W2: [1024,512] -> W2^T [512,1024]
        int bx = (idx & 15) * 32, by = (idx >> 4) * 32;
        transpose_split_tile(W2, g_W2h, g_W2l, D_HID, D_IN, bx, by, tbuf);
    }
}

// ============================================================================
// CSR build: hist (launch 1), single-kernel scan w/ atomic base (launch 2),
// scatter (launch 3). Segment offsets are NOT monotonic in node id — fine,
// aggregate uses g_off[node] + g_cnt[node].
// ============================================================================
__global__ void hist_kernel(const int* __restrict__ dst) {
    int i = blockIdx.x * blockDim.x + threadIdx.x;
    if (i < N_EDGES) atomicAdd(&g_cnt[dst[i]], 1);
}

__global__ void scan_atomic_kernel() {
    __shared__ int ws[8];
    __shared__ int blkbase;
    int t = threadIdx.x, b = blockIdx.x;
    int i = b * 256 + t;
    int v = (i < N_NODES) ? g_cnt[i] : 0;
    int x = v;
    #pragma unroll
    for (int o = 1; o < 32; o <<= 1) {
        int y = __shfl_up_sync(0xFFFFFFFFu, x, o);
        if ((t & 31) >= o) x += y;
    }
    if ((t & 31) == 31) ws[t >> 5] = x;
    __syncthreads();
    if (t == 0) {
        int s = 0;
        #pragma unroll
        for (int j = 0; j < 8; j++) { int tmp = ws[j]; ws[j] = s; s += tmp; }
        blkbase = atomicAdd(&g_base_ctr, s);
    }
    __syncthreads();
    int ex = blkbase + ws[t >> 5] + x - v;
    if (i < N_NODES) { g_off[i] = ex; g_cur[i] = ex; }
}

__global__ void scatter_kernel(const int* __restrict__ src, const int* __restrict__ dst) {
    int i = blockIdx.x * blockDim.x + threadIdx.x;
    if (i < N_EDGES) {
        int d = dst[i];
        int p = atomicAdd(&g_cur[d], 1);
        g_csr[p] = src[i];
    }
}

// ============================================================================
// Aggregate (launch 4): warp-per-node gather-sum + GIN combine -> split fp16
// ============================================================================
__device__ __forceinline__ void f4add(float4& a, const float4 b) {
    a.x += b.x; a.y += b.y; a.z += b.z; a.w += b.w;
}

__device__ __forceinline__ void store_split4(__half* ph, __half* pl, size_t off, float4 v) {
    __half hx, hy, hz, hw, lx, ly, lz, lw;
    split_h(v.x, hx, lx); split_h(v.y, hy, ly);
    split_h(v.z, hz, lz); split_h(v.w, hw, lw);
    *(__half2*)(ph + off)     = __halves2half2(hx, hy);
    *(__half2*)(ph + off + 2) = __halves2half2(hz, hw);
    *(__half2*)(pl + off)     = __halves2half2(lx, ly);
    *(__half2*)(pl + off + 2) = __halves2half2(lz, lw);
}

__global__ __launch_bounds__(256) void aggregate_kernel(const float* __restrict__ feat,
                                                        const float* __restrict__ eps) {
    int wid = threadIdx.x >> 5, lane = threadIdx.x & 31;
    int node = blockIdx.x * 8 + wid;
    if (node >= N_NODES) return;

    float4 a0 = make_float4(0.f, 0.f, 0.f, 0.f), a1 = a0, a2 = a0, a3 = a0;
    int e = g_off[node], e1 = e + g_cnt[node];
    const float4* F = (const float4*)feat;

    for (; e + 1 < e1; e += 2) {
        const float4* p0 = F + (size_t)g_csr[e]     * (D_IN / 4);
        const float4* p1 = F + (size_t)g_csr[e + 1] * (D_IN / 4);
        float4 v00 = p0[lane], v01 = p0[lane + 32], v02 = p0[lane + 64], v03 = p0[lane + 96];
        float4 v10 = p1[lane], v11 = p1[lane + 32], v12 = p1[lane + 64], v13 = p1[lane + 96];
        f4add(a0, v00); f4add(a1, v01); f4add(a2, v02); f4add(a3, v03);
        f4add(a0, v10); f4add(a1, v11); f4add(a2, v12); f4add(a3, v13);
    }
    if (e < e1) {
        const float4* p0 = F + (size_t)g_csr[e] * (D_IN / 4);
        f4add(a0, p0[lane]); f4add(a1, p0[lane + 32]);
        f4add(a2, p0[lane + 64]); f4add(a3, p0[lane + 96]);
    }

    float ep = 1.0f + eps[0];
    const float4* fn = F + (size_t)node * (D_IN / 4);
    float4 f0 = fn[lane], f1 = fn[lane + 32], f2 = fn[lane + 64], f3 = fn[lane + 96];
    float4 r0 = make_float4(fmaf(ep, f0.x, a0.x), fmaf(ep, f0.y, a0.y), fmaf(ep, f0.z, a0.z), fmaf(ep, f0.w, a0.w));
    float4 r1 = make_float4(fmaf(ep, f1.x, a1.x), fmaf(ep, f1.y, a1.y), fmaf(ep, f1.z, a1.z), fmaf(ep, f1.w, a1.w));
    float4 r2 = make_float4(fmaf(ep, f2.x, a2.x), fmaf(ep, f2.y, a2.y), fmaf(ep, f2.z, a2.z), fmaf(ep, f2.w, a2.w));
    float4 r3 = make_float4(fmaf(ep, f3.x, a3.x), fmaf(ep, f3.y, a3.y), fmaf(ep, f3.z, a3.z), fmaf(ep, f3.w, a3.w));

    size_t base = (size_t)node * D_IN;
    store_split4(g_Ah, g_Al, base + lane * 4,        r0);
    store_split4(g_Ah, g_Al, base + (lane + 32) * 4, r1);
    store_split4(g_Ah, g_Al, base + (lane + 64) * 4, r2);
    store_split4(g_Ah, g_Al, base + (lane + 96) * 4, r3);
}

// ============================================================================
// 3xFP16 mma.sync GEMM (R4-proven config): BM=128, BN=128, BK=32, 256 thr
// (8 warps 2x4, 64x32 warp tiles), cp.async double buffer, 80B-padded rows.
// acc += Ah*Bh + Ah*Bl + Al*Bh  (f32 accum; lo*lo dropped).
// ============================================================================
#define BM 128
#define BN 128
#define BK 32
#define HROW 40                       // halfs per smem row (32 + 4 pad = 80B)
#define HTILE_H (BM * HROW)           // halfs per tile (5120)
#define HTILE_B (HTILE_H * 2)         // bytes per tile (10240)
#define STAGE_B (4 * HTILE_B)         // Ah,Al,Bh,Bl per stage (40960)
#define GEMM_SMEM (2 * STAGE_B)       // 81920

__device__ __forceinline__ void cp_async16(uint32_t dst, const void* src, int src_sz) {
    asm volatile("cp.async.ca.shared.global [%0], [%1], 16, %2;"
                 :: "r"(dst), "l"(src), "r"(src_sz));
}

__device__ __forceinline__ void load_tile(uint32_t sbase,
                                          const __half* __restrict__ Ah, const __half* __restrict__ Al,
                                          const __half* __restrict__ Bh, const __half* __restrict__ Bl,
                                          int M, int K, int m0, int n0, int k0, int tid) {
    #pragma unroll
    for (int i = 0; i < 2; i++) {
        int idx = tid + i * 256;
        int row = idx >> 2, c8 = idx & 3;
        uint32_t doff = (uint32_t)(row * (HROW * 2) + c8 * 16);
        int gm = m0 + row;
        int ok = gm < M;
        size_t aoff = (size_t)(ok ? gm : 0) * K + k0 + c8 * 8;
        size_t boff = (size_t)(n0 + row) * K + k0 + c8 * 8;
        cp_async16(sbase + doff,                Ah + aoff, ok ? 16 : 0);
        cp_async16(sbase + HTILE_B + doff,      Al + aoff, ok ? 16 : 0);
        cp_async16(sbase + 2 * HTILE_B + doff,  Bh + boff, 16);
        cp_async16(sbase + 3 * HTILE_B + doff,  Bl + boff, 16);
    }
}

__device__ __forceinline__ void mma_f16(float d[4], const uint32_t a[4], const uint32_t b[2]) {
    asm volatile(
        "mma.sync.aligned.m16n8k16.row.col.f32.f16.f16.f32 "
        "{%0,%1,%2,%3}, {%4,%5,%6,%7}, {%8,%9}, {%0,%1,%2,%3};"
        : "+f"(d[0]), "+f"(d[1]), "+f"(d[2]), "+f"(d[3])
        : "r"(a[0]), "r"(a[1]), "r"(a[2]), "r"(a[3]), "r"(b[0]), "r"(b[1]));
}

__global__ __launch_bounds__(256, 2) void gemm_3xh_kernel(
    const __half* __restrict__ Ah, const __half* __restrict__ Al,
    const __half* __restrict__ Bh, const __half* __restrict__ Bl,
    const float* __restrict__ bias, const float* __restrict__ residual,
    float* __restrict__ out, __half* __restrict__ outh, __half* __restrict__ outl,
    int M, int K, int N, int do_relu)
{
    extern __shared__ char smem[];
    uint32_t sb = smem_to_u32(smem);
    const int tid = threadIdx.x, wid = tid >> 5, lane = tid & 31;
    const int m0 = blockIdx.y * BM, n0 = blockIdx.x * BN;
    const int wm = wid & 1, wn = wid >> 1;       // warp tile: 64 (m) x 32 (n)
    const int lg = lane >> 2, lt = lane & 3;

    float acc[4][4][4];
    #pragma unroll
    for (int i = 0; i < 4; i++)
        #pragma unroll
        for (int j = 0; j < 4; j++)
            #pragma unroll
            for (int c = 0; c < 4; c++) acc[i][j][c] = 0.f;

    const int nk = K / BK;
    load_tile(sb, Ah, Al, Bh, Bl, M, K, m0, n0, 0, tid);
    asm volatile("cp.async.commit_group;" ::: "memory");
    if (nk > 1) load_tile(sb + STAGE_B, Ah, Al, Bh, Bl, M, K, m0, n0, BK, tid);
    asm volatile("cp.async.commit_group;" ::: "memory");

    for (int kc = 0; kc < nk; kc++) {
        asm volatile("cp.async.wait_group 1;" ::: "memory");
        __syncthreads();
        const int buf = kc & 1;
        const __half* tAh = (const __half*)(smem + buf * STAGE_B);
        const __half* tAl = tAh + HTILE_H;
        const __half* tBh = tAl + HTILE_H;
        const __half* tBl = tBh + HTILE_H;

        #pragma unroll
        for (int kk = 0; kk < BK; kk += 16) {
            uint32_t bh[4][2], bl[4][2];
            #pragma unroll
            for (int nj = 0; nj < 4; nj++) {
                int n = wn * 32 + nj * 8 + lg;
                int o = n * HROW + kk + 2 * lt;
                bh[nj][0] = *(const uint32_t*)(tBh + o);
                bh[nj][1] = *(const uint32_t*)(tBh + o + 8);
                bl[nj][0] = *(const uint32_t*)(tBl + o);
                bl[nj][1] = *(const uint32_t*)(tBl + o + 8);
            }
            #pragma unroll
            for (int mi = 0; mi < 4; mi++) {
                int r0 = wm * 64 + mi * 16 + lg;
                int o = r0 * HROW + kk + 2 * lt;
                uint32_t ah[4], al[4];
                ah[0] = *(const uint32_t*)(tAh + o);
                ah[1] = *(const uint32_t*)(tAh + o + 8 * HROW);
                ah[2] = *(const uint32_t*)(tAh + o + 8);
                ah[3] = *(const uint32_t*)(tAh + o + 8 * HROW + 8);
                al[0] = *(const uint32_t*)(tAl + o);
                al[1] = *(const uint32_t*)(tAl + o + 8 * HROW);
                al[2] = *(const uint32_t*)(tAl + o + 8);
                al[3] = *(const uint32_t*)(tAl + o + 8 * HROW + 8);
                #pragma unroll
                for (int nj = 0; nj < 4; nj++) {
                    mma_f16(acc[mi][nj], ah, bl[nj]);   // hi*lo
                    mma_f16(acc[mi][nj], al, bh[nj]);   // lo*hi
                    mma_f16(acc[mi][nj], ah, bh[nj]);   // hi*hi
                }
            }
        }
        __syncthreads();
        if (kc + 2 < nk)
            load_tile(sb + (kc & 1) * STAGE_B, Ah, Al, Bh, Bl, M, K, m0, n0, (kc + 2) * BK, tid);
        asm volatile("cp.async.commit_group;" ::: "memory");
    }

    // ---- Epilogue
    #pragma unroll
    for (int mi = 0; mi < 4; mi++) {
        #pragma unroll
        for (int half = 0; half < 2; half++) {
            int gm = m0 + wm * 64 + mi * 16 + lg + half * 8;
            if (gm >= M) continue;
            #pragma unroll
            for (int nj = 0; nj < 4; nj++) {
                int gn = n0 + wn * 32 + nj * 8 + 2 * lt;
                float vx = acc[mi][nj][half * 2 + 0];
                float vy = acc[mi][nj][half * 2 + 1];
                float2 bv = *(const float2*)(bias + gn);
                vx += bv.x; vy += bv.y;
                if (do_relu) { vx = fmaxf(vx, 0.f); vy = fmaxf(vy, 0.f); }
                if (outh) {
                    __half hx, hy, lx, ly;
                    split_h(vx, hx, lx); split_h(vy, hy, ly);
                    *(__half2*)(outh + (size_t)gm * N + gn) = __halves2half2(hx, hy);
                    *(__half2*)(outl + (size_t)gm * N + gn) = __halves2half2(lx, ly);
                } else {
                    if (residual) {
                        float2 rv = *(const float2*)(residual + (size_t)gm * N + gn);
                        vx += rv.x; vy += rv.y;
                    }
                    *(float2*)(out + (size_t)gm * N + gn) = make_float2(vx, vy);
                }
            }
        }
    }
}

// ============================================================================
// kernel_launch — 7 launches; gemm1 is launch index 5 (ncu -s 5 target).
// ============================================================================
extern "C" void kernel_launch(void* const* d_in, const int* in_sizes, int n_in,
                              void* d_out, int out_size) {
    const float* feat = (const float*)d_in[0];
    const float* W1   = (const float*)d_in[1];
    const float* b1   = (const float*)d_in[2];
    const float* W2   = (const float*)d_in[3];
    const float* b2   = (const float*)d_in[4];
    const float* eps  = (const float*)d_in[5];
    const int*   src  = (const int*)d_in[6];
    const int*   dst  = (const int*)d_in[7];
    float* out = (float*)d_out;

    __half *p_Ah, *p_Al, *p_Hh, *p_Hl, *p_W1h, *p_W1l, *p_W2h, *p_W2l;
    cudaGetSymbolAddress((void**)&p_Ah,  g_Ah);
    cudaGetSymbolAddress((void**)&p_Al,  g_Al);
    cudaGetSymbolAddress((void**)&p_Hh,  g_Hh);
    cudaGetSymbolAddress((void**)&p_Hl,  g_Hl);
    cudaGetSymbolAddress((void**)&p_W1h, g_W1h);
    cudaGetSymbolAddress((void**)&p_W1l, g_W1l);
    cudaGetSymbolAddress((void**)&p_W2h, g_W2h);
    cudaGetSymbolAddress((void**)&p_W2l, g_W2l);

    cudaFuncSetAttribute(gemm_3xh_kernel,
                         cudaFuncAttributeMaxDynamicSharedMemorySize, GEMM_SMEM);

    // 0: prep (zero counts + counter + weight transposes)
    prep_kernel<<<NB_SCAN + 1024, dim3(32, 8)>>>(W1, W2);
    // 1-3: CSR build
    hist_kernel<<<N_EDGES / 256, 256>>>(dst);
    scan_atomic_kernel<<<NB_SCAN, 256>>>();
    scatter_kernel<<<N_EDGES / 256, 256>>>(src, dst);
    // 4: aggregate + GIN combine (writes split rst)
    aggregate_kernel<<<(N_NODES + 7) / 8, 256>>>(feat, eps);
    // 5: GEMM1: H = relu(rst @ W1 + b1), split output  [10000,512]@[512,1024]
    gemm_3xh_kernel<<<dim3(D_HID / BN, (N_NODES + BM - 1) / BM), 256, GEMM_SMEM>>>(
        p_Ah, p_Al, p_W1h, p_W1l, b1, nullptr, nullptr, p_Hh, p_Hl,
        N_NODES, D_IN, D_HID, 1);
    // 6: GEMM2: out = H @ W2 + b2 + feat  [10000,1024]@[1024,512]
    gemm_3xh_kernel<<<dim3(D_IN / BN, (N_NODES + BM - 1) / BM), 256, GEMM_SMEM>>>(
        p_Hh, p_Hl, p_W2h, p_W2l, b2, feat, out, nullptr, nullptr,
        N_NODES, D_HID, D_IN, 0);
}

// round 8
// speedup vs baseline: 1.3222x; 1.1727x over previous
#include <cuda_runtime.h>
#include <cuda_fp16.h>
#include <cstdint>

// ============================================================================
// Problem constants
// ============================================================================
#define N_NODES 10000
#define N_EDGES 160000
#define D_IN    512
#define D_HID   1024
#define NB_SCAN 40          // ceil(N_NODES/256)
#define NMB     79          // ceil(N_NODES/128) M-blocks

// Persistent tile queue layout
#define TILE_AGG_END 316    // 79 * 4 agg sub-tiles (32 nodes each)
#define TILE_G1_END  948    // + 79 * 8 GEMM1 tiles
#define TILE_TOTAL   1580   // + 79 * 8 GEMM2 half-K chunks
#define GRID_P       304    // 2 CTAs/SM on 152 SMs; all-resident either way

// ============================================================================
// Scratch (static __device__ arrays — no allocation allowed)
// ============================================================================
__device__ __half g_Ah[(size_t)N_NODES * D_IN];    // rst hi   [N, 512]
__device__ __half g_Al[(size_t)N_NODES * D_IN];    // rst lo
__device__ __half g_Hh[(size_t)N_NODES * D_HID];   // hidden hi [N, 1024]
__device__ __half g_Hl[(size_t)N_NODES * D_HID];   // hidden lo
__device__ __half g_W1h[(size_t)D_HID * D_IN];     // W1^T hi [1024, 512]
__device__ __half g_W1l[(size_t)D_HID * D_IN];
__device__ __half g_W2h[(size_t)D_IN * D_HID];     // W2^T hi [512, 1024]
__device__ __half g_W2l[(size_t)D_IN * D_HID];
__device__ int   g_cnt[N_NODES];
__device__ int   g_off[N_NODES];
__device__ int   g_cur[N_NODES];
__device__ int   g_csr[N_EDGES];
__device__ int   g_base_ctr;
__device__ int   g_qhead;
__device__ int   g_adone[NMB];
__device__ int   g_hdone[NMB];

// ============================================================================
// Helpers
// ============================================================================
__device__ __forceinline__ uint32_t smem_to_u32(const void* p) {
    uint32_t a;
    asm("{ .reg .u64 t; cvta.to.shared.u64 t, %1; cvt.u32.u64 %0, t; }" : "=r"(a) : "l"(p));
    return a;
}

__device__ __forceinline__ void split_h(float x, __half& h, __half& l) {
    h = __float2half_rn(x);
    l = __float2half_rn(x - __half2float(h));
}

__device__ __forceinline__ void wait_flag(volatile int* f, int target) {
    while (*f < target) __nanosleep(64);
    __threadfence();   // acquire: order subsequent reads after observed flag
}

// ============================================================================
// prep_kernel (launch 0): zero counts/flags/queue + both W transposes.
// ============================================================================
__device__ __forceinline__ void transpose_split_tile(const float* __restrict__ in,
                                                     __half* __restrict__ outh,
                                                     __half* __restrict__ outl,
                                                     int R, int C, int bx, int by,
                                                     float* tbuf /* 32*33 */) {
    int tx = threadIdx.x, ty = threadIdx.y;
    #pragma unroll
    for (int j = 0; j < 32; j += 8)
        tbuf[(ty + j) * 33 + tx] = in[(size_t)(by + ty + j) * C + bx + tx];
    __syncthreads();
    #pragma unroll
    for (int j = 0; j < 32; j += 8) {
        float x = tbuf[tx * 33 + ty + j];
        __half h, l; split_h(x, h, l);
        size_t o = (size_t)(bx + ty + j) * R + by + tx;
        outh[o] = h; outl[o] = l;
    }
}

__global__ void prep_kernel(const float* __restrict__ W1, const float* __restrict__ W2) {
    __shared__ float tbuf[32 * 33];
    int b = blockIdx.x;
    int t = threadIdx.y * 32 + threadIdx.x;
    if (b < NB_SCAN) {
        int i = b * 256 + t;
        if (i < N_NODES) g_cnt[i] = 0;
        if (b == 0) {
            if (t < NMB) { g_adone[t] = 0; g_hdone[t] = 0; }
            if (t == 200) { g_base_ctr = 0; g_qhead = 0; }
        }
    } else if (b < NB_SCAN + 512) {
        int idx = b - NB_SCAN;                     // W1: [512,1024] -> W1^T [1024,512]
        int bx = (idx & 31) * 32, by = (idx >> 5) * 32;
        transpose_split_tile(W1, g_W1h, g_W1l, D_IN, D_HID, bx, by, tbuf);
    } else {
        int idx = b - NB_SCAN - 512;               // W2: [1024,512] -> W2^T [512,1024]
        int bx = (idx & 15) * 32, by = (idx >> 4) * 32;
        transpose_split_tile(W2, g_W2h, g_W2l, D_HID, D_IN, bx, by, tbuf);
    }
}

// ============================================================================
// CSR build (launches 1-3)
// ============================================================================
__global__ void hist_kernel(const int* __restrict__ dst) {
    int i = blockIdx.x * blockDim.x + threadIdx.x;
    if (i < N_EDGES) atomicAdd(&g_cnt[dst[i]], 1);
}

__global__ void scan_atomic_kernel() {
    __shared__ int ws[8];
    __shared__ int blkbase;
    int t = threadIdx.x, b = blockIdx.x;
    int i = b * 256 + t;
    int v = (i < N_NODES) ? g_cnt[i] : 0;
    int x = v;
    #pragma unroll
    for (int o = 1; o < 32; o <<= 1) {
        int y = __shfl_up_sync(0xFFFFFFFFu, x, o);
        if ((t & 31) >= o) x += y;
    }
    if ((t & 31) == 31) ws[t >> 5] = x;
    __syncthreads();
    if (t == 0) {
        int s = 0;
        #pragma unroll
        for (int j = 0; j < 8; j++) { int tmp = ws[j]; ws[j] = s; s += tmp; }
        blkbase = atomicAdd(&g_base_ctr, s);
    }
    __syncthreads();
    int ex = blkbase + ws[t >> 5] + x - v;
    if (i < N_NODES) { g_off[i] = ex; g_cur[i] = ex; }
}

__global__ void scatter_kernel(const int* __restrict__ src, const int* __restrict__ dst) {
    int i = blockIdx.x * blockDim.x + threadIdx.x;
    if (i < N_EDGES) {
        int d = dst[i];
        int p = atomicAdd(&g_cur[d], 1);
        g_csr[p] = src[i];
    }
}

// ============================================================================
// Aggregate sub-tile body: one node per call (one warp). Also pre-inits
// out[node] = feat[node] + b2 (bias + residual for GEMM2's split-K RED adds).
// ============================================================================
__device__ __forceinline__ void f4add(float4& a, const float4 b) {
    a.x += b.x; a.y += b.y; a.z += b.z; a.w += b.w;
}

__device__ __forceinline__ void store_split4(__half* ph, __half* pl, size_t off, float4 v) {
    __half hx, hy, hz, hw, lx, ly, lz, lw;
    split_h(v.x, hx, lx); split_h(v.y, hy, ly);
    split_h(v.z, hz, lz); split_h(v.w, hw, lw);
    *(__half2*)(ph + off)     = __halves2half2(hx, hy);
    *(__half2*)(ph + off + 2) = __halves2half2(hz, hw);
    *(__half2*)(pl + off)     = __halves2half2(lx, ly);
    *(__half2*)(pl + off + 2) = __halves2half2(lz, lw);
}

__device__ __forceinline__ void agg_node(int node, int lane,
                                         const float* __restrict__ feat, float ep,
                                         const float* __restrict__ b2,
                                         float* __restrict__ out) {
    float4 a0 = make_float4(0.f, 0.f, 0.f, 0.f), a1 = a0, a2 = a0, a3 = a0;
    int e = g_off[node], e1 = e + g_cnt[node];
    const float4* F = (const float4*)feat;

    for (; e + 1 < e1; e += 2) {
        const float4* p0 = F + (size_t)g_csr[e]     * (D_IN / 4);
        const float4* p1 = F + (size_t)g_csr[e + 1] * (D_IN / 4);
        float4 v00 = p0[lane], v01 = p0[lane + 32], v02 = p0[lane + 64], v03 = p0[lane + 96];
        float4 v10 = p1[lane], v11 = p1[lane + 32], v12 = p1[lane + 64], v13 = p1[lane + 96];
        f4add(a0, v00); f4add(a1, v01); f4add(a2, v02); f4add(a3, v03);
        f4add(a0, v10); f4add(a1, v11); f4add(a2, v12); f4add(a3, v13);
    }
    if (e < e1) {
        const float4* p0 = F + (size_t)g_csr[e] * (D_IN / 4);
        f4add(a0, p0[lane]); f4add(a1, p0[lane + 32]);
        f4add(a2, p0[lane + 64]); f4add(a3, p0[lane + 96]);
    }

    const float4* fn = F + (size_t)node * (D_IN / 4);
    const float4* B2 = (const float4*)b2;
    float4* O = (float4*)out + (size_t)node * (D_IN / 4);
    size_t base = (size_t)node * D_IN;
    #pragma unroll
    for (int q = 0; q < 4; q++) {
        float4 f = fn[lane + 32 * q];
        float4 a = (q == 0) ? a0 : (q == 1) ? a1 : (q == 2) ? a2 : a3;
        float4 r = make_float4(fmaf(ep, f.x, a.x), fmaf(ep, f.y, a.y),
                               fmaf(ep, f.z, a.z), fmaf(ep, f.w, a.w));
        store_split4(g_Ah, g_Al, base + (lane + 32 * q) * 4, r);
        float4 bb = B2[lane + 32 * q];
        O[lane + 32 * q] = make_float4(f.x + bb.x, f.y + bb.y, f.z + bb.z, f.w + bb.w);
    }
}

// ============================================================================
// 3xFP16 GEMM tile body: 128x128 output, K=512 loop, double-buffered cp.async,
// 80B-padded rows (word-bank conflict-free). acc += Ah*Bh + Ah*Bl + Al*Bh.
// mode: outH != nullptr -> GEMM1 epilogue (bias+relu, split store to H)
//       else            -> GEMM2 chunk epilogue (atomicAdd fp32 into out)
// ============================================================================
#define BM 128
#define BN 128
#define BK 32
#define KLOOP 512
#define HROW 40                       // halfs per smem row (32 + 4 pad = 80B)
#define HTILE_H (BM * HROW)           // 5120 halfs per tile
#define HTILE_B (HTILE_H * 2)         // 10240 bytes
#define STAGE_B (4 * HTILE_B)         // Ah,Al,Bh,Bl = 40960
#define GEMM_SMEM (2 * STAGE_B)       // 81920

__device__ __forceinline__ void cp_async16(uint32_t dst, const void* src, int src_sz) {
    asm volatile("cp.async.ca.shared.global [%0], [%1], 16, %2;"
                 :: "r"(dst), "l"(src), "r"(src_sz));
}

__device__ __forceinline__ void load_tile_p(uint32_t sbase,
                                            const __half* __restrict__ Ah, const __half* __restrict__ Al,
                                            const __half* __restrict__ Bh, const __half* __restrict__ Bl,
                                            int lda, int ldb, int m0, int n0, int k0, int tid) {
    #pragma unroll
    for (int i = 0; i < 2; i++) {
        int idx = tid + i * 256;
        int row = idx >> 2, c8 = idx & 3;
        uint32_t doff = (uint32_t)(row * (HROW * 2) + c8 * 16);
        int gm = m0 + row;
        int ok = gm < N_NODES;
        size_t aoff = (size_t)(ok ? gm : 0) * lda + k0 + c8 * 8;
        size_t boff = (size_t)(n0 + row) * ldb + k0 + c8 * 8;
        cp_async16(sbase + doff,                Ah + aoff, ok ? 16 : 0);
        cp_async16(sbase + HTILE_B + doff,      Al + aoff, ok ? 16 : 0);
        cp_async16(sbase + 2 * HTILE_B + doff,  Bh + boff, 16);
        cp_async16(sbase + 3 * HTILE_B + doff,  Bl + boff, 16);
    }
}

__device__ __forceinline__ void mma_f16(float d[4], const uint32_t a[4], const uint32_t b[2]) {
    asm volatile(
        "mma.sync.aligned.m16n8k16.row.col.f32.f16.f16.f32 "
        "{%0,%1,%2,%3}, {%4,%5,%6,%7}, {%8,%9}, {%0,%1,%2,%3};"
        : "+f"(d[0]), "+f"(d[1]), "+f"(d[2]), "+f"(d[3])
        : "r"(a[0]), "r"(a[1]), "r"(a[2]), "r"(a[3]), "r"(b[0]), "r"(b[1]));
}

__device__ __forceinline__ void gemm_tile_body(
    char* smem, uint32_t sb, int tid,
    const __half* __restrict__ Ah, const __half* __restrict__ Al, int lda,
    const __half* __restrict__ Bh, const __half* __restrict__ Bl, int ldb,
    int m0, int n0,
    const float* __restrict__ bias,
    float* __restrict__ outp,
    __half* __restrict__ outH, __half* __restrict__ outL, int outld)
{
    const int wid = tid >> 5, lane = tid & 31;
    const int wm = wid & 1, wn = wid >> 1;       // warp tile: 64 (m) x 32 (n)
    const int lg = lane >> 2, lt = lane & 3;

    float acc[4][4][4];
    #pragma unroll
    for (int i = 0; i < 4; i++)
        #pragma unroll
        for (int j = 0; j < 4; j++)
            #pragma unroll
            for (int c = 0; c < 4; c++) acc[i][j][c] = 0.f;

    const int nk = KLOOP / BK;  // 16
    load_tile_p(sb, Ah, Al, Bh, Bl, lda, ldb, m0, n0, 0, tid);
    asm volatile("cp.async.commit_group;" ::: "memory");
    load_tile_p(sb + STAGE_B, Ah, Al, Bh, Bl, lda, ldb, m0, n0, BK, tid);
    asm volatile("cp.async.commit_group;" ::: "memory");

    for (int kc = 0; kc < nk; kc++) {
        asm volatile("cp.async.wait_group 1;" ::: "memory");
        __syncthreads();
        const int buf = kc & 1;
        const __half* tAh = (const __half*)(smem + buf * STAGE_B);
        const __half* tAl = tAh + HTILE_H;
        const __half* tBh = tAl + HTILE_H;
        const __half* tBl = tBh + HTILE_H;

        #pragma unroll
        for (int kk = 0; kk < BK; kk += 16) {
            uint32_t bh[4][2], bl[4][2];
            #pragma unroll
            for (int nj = 0; nj < 4; nj++) {
                int n = wn * 32 + nj * 8 + lg;
                int o = n * HROW + kk + 2 * lt;
                bh[nj][0] = *(const uint32_t*)(tBh + o);
                bh[nj][1] = *(const uint32_t*)(tBh + o + 8);
                bl[nj][0] = *(const uint32_t*)(tBl + o);
                bl[nj][1] = *(const uint32_t*)(tBl + o + 8);
            }
            #pragma unroll
            for (int mi = 0; mi < 4; mi++) {
                int r0 = wm * 64 + mi * 16 + lg;
                int o = r0 * HROW + kk + 2 * lt;
                uint32_t ah[4], al[4];
                ah[0] = *(const uint32_t*)(tAh + o);
                ah[1] = *(const uint32_t*)(tAh + o + 8 * HROW);
                ah[2] = *(const uint32_t*)(tAh + o + 8);
                ah[3] = *(const uint32_t*)(tAh + o + 8 * HROW + 8);
                al[0] = *(const uint32_t*)(tAl + o);
                al[1] = *(const uint32_t*)(tAl + o + 8 * HROW);
                al[2] = *(const uint32_t*)(tAl + o + 8);
                al[3] = *(const uint32_t*)(tAl + o + 8 * HROW + 8);
                #pragma unroll
                for (int nj = 0; nj < 4; nj++) {
                    mma_f16(acc[mi][nj], ah, bl[nj]);   // hi*lo
                    mma_f16(acc[mi][nj], al, bh[nj]);   // lo*hi
                    mma_f16(acc[mi][nj], ah, bh[nj]);   // hi*hi
                }
            }
        }
        __syncthreads();
        if (kc + 2 < nk)
            load_tile_p(sb + (kc & 1) * STAGE_B, Ah, Al, Bh, Bl, lda, ldb,
                        m0, n0, (kc + 2) * BK, tid);
        asm volatile("cp.async.commit_group;" ::: "memory");
    }
    asm volatile("cp.async.wait_group 0;" ::: "memory");  // drain before smem reuse

    // ---- Epilogue
    #pragma unroll
    for (int mi = 0; mi < 4; mi++) {
        #pragma unroll
        for (int half = 0; half < 2; half++) {
            int gm = m0 + wm * 64 + mi * 16 + lg + half * 8;
            if (gm >= N_NODES) continue;
            #pragma unroll
            for (int nj = 0; nj < 4; nj++) {
                int gn = n0 + wn * 32 + nj * 8 + 2 * lt;
                float vx = acc[mi][nj][half * 2 + 0];
                float vy = acc[mi][nj][half * 2 + 1];
                if (outH) {
                    float2 bv = *(const float2*)(bias + gn);
                    vx = fmaxf(vx + bv.x, 0.f);
                    vy = fmaxf(vy + bv.y, 0.f);
                    __half hx, hy, lx, ly;
                    split_h(vx, hx, lx); split_h(vy, hy, ly);
                    *(__half2*)(outH + (size_t)gm * outld + gn) = __halves2half2(hx, hy);
                    *(__half2*)(outL + (size_t)gm * outld + gn) = __halves2half2(lx, ly);
                } else {
                    atomicAdd(outp + (size_t)gm * D_IN + gn,     vx);
                    atomicAdd(outp + (size_t)gm * D_IN + gn + 1, vy);
                }
            }
        }
    }
}

// ============================================================================
// Persistent fused kernel (launch 4): agg -> GEMM1 -> GEMM2 via atomic queue
// ============================================================================
__global__ __launch_bounds__(256, 2) void fused_kernel(
    const float* __restrict__ feat, const float* __restrict__ eps,
    const float* __restrict__ b1, const float* __restrict__ b2,
    float* __restrict__ out)
{
    extern __shared__ char smem[];
    __shared__ int s_t;
    uint32_t sb = smem_to_u32(smem);
    const int tid = threadIdx.x, wid = tid >> 5, lane = tid & 31;

    for (;;) {
        __syncthreads();
        if (tid == 0) s_t = atomicAdd(&g_qhead, 1);
        __syncthreads();
        int t = s_t;
        if (t >= TILE_TOTAL) return;

        if (t < TILE_AGG_END) {
            // ---- aggregate sub-tile: 32 nodes (4 per warp) + out pre-init
            float ep = 1.0f + eps[0];
            int base = t * 32;
            #pragma unroll
            for (int i = 0; i < 4; i++) {
                int node = base + wid * 4 + i;
                if (node < N_NODES) agg_node(node, lane, feat, ep, b2, out);
            }
            __threadfence();
            __syncthreads();
            if (tid == 0) atomicAdd(&g_adone[t >> 2], 1);
        } else if (t < TILE_G1_END) {
            // ---- GEMM1 tile: H[m,n] = relu(rst @ W1 + b1), split-stored
            int u = t - TILE_AGG_END;
            int m = u >> 3, n = u & 7;
            wait_flag(&g_adone[m], 4);
            gemm_tile_body(smem, sb, tid,
                           g_Ah, g_Al, D_IN, g_W1h, g_W1l, D_IN,
                           m * 128, n * 128, b1, nullptr, g_Hh, g_Hl, D_HID);
            __threadfence();
            __syncthreads();
            if (tid == 0) atomicAdd(&g_hdone[m], 1);
        } else {
            // ---- GEMM2 half-K chunk: out[m,n2] += H[:,kc*512:+512] @ W2chunk
            int u = t - TILE_G1_END;
            int m = u >> 3, r = u & 7, n2 = r >> 1, kc = r & 1;
            wait_flag(&g_hdone[m], 8);
            gemm_tile_body(smem, sb, tid,
                           g_Hh + kc * 512, g_Hl + kc * 512, D_HID,
                           g_W2h + kc * 512, g_W2l + kc * 512, D_HID,
                           m * 128, n2 * 128, nullptr, out, nullptr, nullptr, 0);
        }
    }
}

// ============================================================================
// kernel_launch — 5 launches
// ============================================================================
extern "C" void kernel_launch(void* const* d_in, const int* in_sizes, int n_in,
                              void* d_out, int out_size) {
    const float* feat = (const float*)d_in[0];
    const float* W1   = (const float*)d_in[1];
    const float* b1   = (const float*)d_in[2];
    const float* W2   = (const float*)d_in[3];
    const float* b2   = (const float*)d_in[4];
    const float* eps  = (const float*)d_in[5];
    const int*   src  = (const int*)d_in[6];
    const int*   dst  = (const int*)d_in[7];
    float* out = (float*)d_out;

    cudaFuncSetAttribute(fused_kernel,
                         cudaFuncAttributeMaxDynamicSharedMemorySize, GEMM_SMEM);

    // 0: prep (zero counts/flags/queue + weight transposes)
    prep_kernel<<<NB_SCAN + 1024, dim3(32, 8)>>>(W1, W2);
    // 1-3: CSR build
    hist_kernel<<<N_EDGES / 256, 256>>>(dst);
    scan_atomic_kernel<<<NB_SCAN, 256>>>();
    scatter_kernel<<<N_EDGES / 256, 256>>>(src, dst);
    // 4: persistent fused aggregate + GEMM1 + GEMM2
    fused_kernel<<<GRID_P, 256, GEMM_SMEM>>>(feat, eps, b1, b2, out);
}